// round 15
// baseline (speedup 1.0000x reference)
#include <cuda_runtime.h>
#include <cuda_fp16.h>
#include <math_constants.h>
#include <cstdint>

#define B 8
#define T 512
#define S 2048
#define L 4
#define NS 1024
#define NH 16
#define HD 64
#define ST (S + T)
#define BT (B * T)

#define QSCALE 0.18033688f   // HD^-0.5 * log2(e)

// Scratch (no allocations allowed)
__device__ __half g_wvh[BT * NS];                   // attention output (half)
__device__ __half g_xh[BT * NS];                    // x as half
__device__ __half g_wth[4 * NS * NS];               // transposed half weights [N][K]
__device__ __half g_kh[(size_t)B * NH * ST * HD];   // packed K [b][h][s][d]
__device__ __half g_vh[(size_t)B * NH * ST * HD];   // packed V [b][h][s][d]
__device__ __half g_qh[(size_t)B * NH * T * HD];    // packed scaled Q [b][h][t][d]

// ---------------------------------------------------------------------------
// helpers
// ---------------------------------------------------------------------------
__device__ __forceinline__ uint32_t smem_u32(const void* p) {
    uint32_t a;
    asm("{ .reg .u64 t; cvta.to.shared.u64 t, %1; cvt.u32.u64 %0, t; }" : "=r"(a) : "l"(p));
    return a;
}
__device__ __forceinline__ void cp_async16_ca(uint32_t saddr, const void* gaddr) {
    asm volatile("cp.async.ca.shared.global [%0], [%1], 16;" :: "r"(saddr), "l"(gaddr));
}
__device__ __forceinline__ void cp_async16_cg(uint32_t saddr, const void* gaddr) {
    asm volatile("cp.async.cg.shared.global [%0], [%1], 16;" :: "r"(saddr), "l"(gaddr));
}
#define CP_COMMIT() asm volatile("cp.async.commit_group;" ::: "memory")
#define CP_WAIT(n)  asm volatile("cp.async.wait_group %0;" :: "n"(n) : "memory")

__device__ __forceinline__ void ldsm_x4(uint32_t& r0, uint32_t& r1, uint32_t& r2, uint32_t& r3,
                                        uint32_t addr) {
    asm volatile("ldmatrix.sync.aligned.m8n8.x4.shared.b16 {%0,%1,%2,%3}, [%4];"
                 : "=r"(r0), "=r"(r1), "=r"(r2), "=r"(r3) : "r"(addr));
}
__device__ __forceinline__ void ldsm_x4_trans(uint32_t& r0, uint32_t& r1, uint32_t& r2, uint32_t& r3,
                                              uint32_t addr) {
    asm volatile("ldmatrix.sync.aligned.m8n8.x4.trans.shared.b16 {%0,%1,%2,%3}, [%4];"
                 : "=r"(r0), "=r"(r1), "=r"(r2), "=r"(r3) : "r"(addr));
}
__device__ __forceinline__ void ldsm_x2_trans(uint32_t& r0, uint32_t& r1, uint32_t addr) {
    asm volatile("ldmatrix.sync.aligned.m8n8.x2.trans.shared.b16 {%0,%1}, [%2];"
                 : "=r"(r0), "=r"(r1) : "r"(addr));
}
__device__ __forceinline__ void mma_f16(float* c, const uint32_t* a, uint32_t b0, uint32_t b1) {
    asm volatile(
        "mma.sync.aligned.m16n8k16.row.col.f32.f16.f16.f32 "
        "{%0,%1,%2,%3}, {%4,%5,%6,%7}, {%8,%9}, {%0,%1,%2,%3};"
        : "+f"(c[0]), "+f"(c[1]), "+f"(c[2]), "+f"(c[3])
        : "r"(a[0]), "r"(a[1]), "r"(a[2]), "r"(a[3]), "r"(b0), "r"(b1));
}
__device__ __forceinline__ uint32_t ex2_h2(uint32_t h) {
    uint32_t r; asm("ex2.approx.f16x2 %0, %1;" : "=r"(r) : "r"(h)); return r;
}

// ---------------------------------------------------------------------------
// x -> half
// ---------------------------------------------------------------------------
__global__ __launch_bounds__(256)
void cvt_xh(const float* __restrict__ in, __half* __restrict__ out, int n4)
{
    int i = blockIdx.x * blockDim.x + threadIdx.x;
    if (i < n4) {
        float4 v = ((const float4*)in)[i];
        __half2 h0 = __floats2half2_rn(v.x, v.y);
        __half2 h1 = __floats2half2_rn(v.z, v.w);
        ((uint2*)out)[i] = make_uint2(*(uint32_t*)&h0, *(uint32_t*)&h1);
    }
}

// ---------------------------------------------------------------------------
// All 4 weight transposes in one launch: dst[z][n][k] = half(src_z[k][n])
// ---------------------------------------------------------------------------
__global__ __launch_bounds__(256)
void transpose_cvt_h(const float* __restrict__ W0, const float* __restrict__ W1,
                     const float* __restrict__ W2, const float* __restrict__ W3,
                     __half* __restrict__ dst)
{
    __shared__ float t[32][33];
    const int tx = threadIdx.x, ty = threadIdx.y;
    const int bx = blockIdx.x * 32;
    const int by = blockIdx.y * 32;
    const int z  = blockIdx.z;
    const float* src = (z == 0) ? W0 : (z == 1) ? W1 : (z == 2) ? W2 : W3;
    __half* out = dst + (size_t)z * NS * NS;
#pragma unroll
    for (int i = 0; i < 32; i += 8)
        t[ty + i][tx] = src[(size_t)(by + ty + i) * NS + bx + tx];
    __syncthreads();
#pragma unroll
    for (int i = 0; i < 32; i += 8)
        out[(size_t)(bx + ty + i) * NS + by + tx] = __float2half_rn(t[tx][ty + i]);
}

// ---------------------------------------------------------------------------
// fp16 mma GEMM, 3-segment output, FUSED KV-cache pack filler CTAs.
// R15: 3-stage cp.async pipeline (prefetch distance 2) — each tile load gets
// two chunk-compute periods to land instead of one.
// ---------------------------------------------------------------------------
#define PHG 72
#define PROWG (PHG * 2)                 // 144 B
#define GTILE_B (128 * PROWG)           // 18432
#define GSTAGE_B (2 * GTILE_B)          // 36864 (A+B per stage)
#define GSM_TOTAL (3 * GSTAGE_B)        // 110592
#define GEMM_XBLKS 24
#define PACK_XBLKS 64                   // 64*32 = 2048 pack CTAs

__global__ __launch_bounds__(256, 2)
void gemm_h3(const __half* __restrict__ A, const __half* __restrict__ Bt,
             const float* __restrict__ b0, const float* __restrict__ b1,
             const float* __restrict__ b2,
             float* __restrict__ Y0, float* __restrict__ Y1, float* __restrict__ Y2,
             __half* __restrict__ pk, __half* __restrict__ pv, __half* __restrict__ pq,
             const float* __restrict__ cache)
{
    extern __shared__ char smc[];
    __shared__ float s_bias[128];

    const uint32_t tid  = threadIdx.x;
    const bool isQKV = (pq != nullptr);

    // ---- filler CTAs: pack fp32 KV cache -> half (s < S rows) ----
    if (isQKV && blockIdx.x >= GEMM_XBLKS) {
        const int pb = (blockIdx.x - GEMM_XBLKS) * 32 + blockIdx.y;   // 0..2047
#pragma unroll
        for (int u = 0; u < 8; u++) {
            int idx = pb * 2048 + u * 256 + (int)tid;
            int d4 = idx & 15;
            int t  = idx >> 4;
            int s  = t % S;
            int bh = t / S;
            int b = bh >> 4, h = bh & 15;
            const float* base = cache + (size_t)b * (L * 2 * S * NS)
                              + (size_t)s * NS + h * HD + d4 * 4;
            float4 k4 = *(const float4*)base;
            float4 v4 = *(const float4*)(base + (size_t)S * NS);
            __half2 k0 = __floats2half2_rn(k4.x, k4.y);
            __half2 k1 = __floats2half2_rn(k4.z, k4.w);
            __half2 v0 = __floats2half2_rn(v4.x, v4.y);
            __half2 v1 = __floats2half2_rn(v4.z, v4.w);
            size_t oidx = ((size_t)bh * ST + s) * 16 + d4;
            ((uint2*)pk)[oidx] = make_uint2(*(uint32_t*)&k0, *(uint32_t*)&k1);
            ((uint2*)pv)[oidx] = make_uint2(*(uint32_t*)&v0, *(uint32_t*)&v1);
        }
        return;
    }

    const uint32_t wid  = tid >> 5;
    const uint32_t lane = tid & 31;
    const int row0 = blockIdx.y * 128;
    const int seg  = blockIdx.x >> 3;
    const int ycol0 = (blockIdx.x & 7) * 128;

    const float* bias = (seg == 0) ? b0 : (seg == 1) ? b1 : b2;
    float* Y = (seg == 0) ? Y0 : (seg == 1) ? Y1 : Y2;

    if (tid < 32) {
        float4 v = bias ? *(const float4*)&bias[ycol0 + tid * 4]
                        : make_float4(0.f, 0.f, 0.f, 0.f);
        *(float4*)&s_bias[tid * 4] = v;
    }

    const uint32_t smBase = smem_u32(smc);
    const __half* Ab = A  + (size_t)row0 * NS;
    const __half* Bb = Bt + (size_t)blockIdx.x * 128 * NS;

    uint32_t stOff[4];
    const __half* gA[4];
    const __half* gB[4];
#pragma unroll
    for (int u = 0; u < 4; u++) {
        int idx = (int)tid + u * 256;
        int r = idx >> 3, c8 = idx & 7;
        stOff[u] = (uint32_t)(r * PROWG + c8 * 16);
        gA[u] = Ab + (size_t)r * NS + c8 * 8;
        gB[u] = Bb + (size_t)r * NS + c8 * 8;
    }

    const uint32_t wm = wid >> 2;
    const uint32_t wn = wid & 3;
    uint32_t offA[4], offB[2];
#pragma unroll
    for (int tm = 0; tm < 4; tm++)
        offA[tm] = (uint32_t)((wm * 64 + tm * 16 + (lane & 15)) * PROWG + (lane >> 4) * 16);
#pragma unroll
    for (int p = 0; p < 2; p++)
        offB[p] = (uint32_t)((wn * 32 + p * 16 + (lane & 7) + ((lane >> 4) & 1) * 8) * PROWG
                             + ((lane >> 3) & 1) * 16 + GTILE_B);

    float acc[4][4][4];
#pragma unroll
    for (int i = 0; i < 4; i++)
#pragma unroll
        for (int j = 0; j < 4; j++)
#pragma unroll
            for (int v = 0; v < 4; v++) acc[i][j][v] = 0.f;

    // prologue: chunks 0,1 -> stages 0,1
#pragma unroll
    for (int c = 0; c < 2; c++) {
        const uint32_t st = smBase + c * GSTAGE_B;
        const int koff = c * 64;
#pragma unroll
        for (int u = 0; u < 4; u++) {
            cp_async16_ca(st + stOff[u], gA[u] + koff);
            cp_async16_ca(st + GTILE_B + stOff[u], gB[u] + koff);
        }
        CP_COMMIT();
    }

    int stage = 0;                 // stage of chunk i
    for (int i = 0; i < 16; i++) {
        // issue chunk i+2 into the stage freed at iteration i-1
        if (i + 2 < 16) {
            int ls = stage + 2; if (ls >= 3) ls -= 3;
            const uint32_t st = smBase + ls * GSTAGE_B;
            const int koff = (i + 2) * 64;
#pragma unroll
            for (int u = 0; u < 4; u++) {
                cp_async16_ca(st + stOff[u], gA[u] + koff);
                cp_async16_ca(st + GTILE_B + stOff[u], gB[u] + koff);
            }
            CP_COMMIT();
            CP_WAIT(2);            // chunks i+1, i+2 may be in flight
        } else if (i + 1 < 16) {
            CP_WAIT(1);
        } else {
            CP_WAIT(0);
        }
        __syncthreads();

        const uint32_t stg = smBase + stage * GSTAGE_B;
#pragma unroll
        for (int ks = 0; ks < 4; ks++) {
            uint32_t af[4][4], bf[4][2];
#pragma unroll
            for (int tm = 0; tm < 4; tm++)
                ldsm_x4(af[tm][0], af[tm][1], af[tm][2], af[tm][3],
                        stg + offA[tm] + ks * 32);
#pragma unroll
            for (int p = 0; p < 2; p++)
                ldsm_x4(bf[2 * p][0], bf[2 * p][1], bf[2 * p + 1][0], bf[2 * p + 1][1],
                        stg + offB[p] + ks * 32);
#pragma unroll
            for (int tm = 0; tm < 4; tm++)
#pragma unroll
                for (int tn = 0; tn < 4; tn++)
                    mma_f16(acc[tm][tn], af[tm], bf[tn][0], bf[tn][1]);
        }
        __syncthreads();           // consumption barrier (stage reusable)
        if (++stage == 3) stage = 0;
    }

    const int rbase = row0 + (int)wm * 64 + (int)(lane >> 2);
    const int cbase = ycol0 + (int)wn * 32 + (int)(lane & 3) * 2;
    const int csb   = (int)wn * 32 + (int)(lane & 3) * 2;

#pragma unroll
    for (int tm = 0; tm < 4; tm++) {
#pragma unroll
        for (int tn = 0; tn < 4; tn++) {
            float b0v = s_bias[csb + tn * 8];
            float b1v = s_bias[csb + tn * 8 + 1];
            float2 v0 = make_float2(acc[tm][tn][0] + b0v, acc[tm][tn][1] + b1v);
            float2 v1 = make_float2(acc[tm][tn][2] + b0v, acc[tm][tn][3] + b1v);
            const int r0 = rbase + tm * 16;
            const int r1 = r0 + 8;
            const int c  = cbase + tn * 8;

            if (!isQKV || seg < 2) {
                *(float2*)(Y + (size_t)r0 * NS + c) = v0;
                *(float2*)(Y + (size_t)r1 * NS + c) = v1;
            }
            if (isQKV) {
                const int hh = c >> 6, dd = c & 63;
                if (seg == 2) {
                    __half2 q0 = __floats2half2_rn(v0.x * QSCALE, v0.y * QSCALE);
                    __half2 q1 = __floats2half2_rn(v1.x * QSCALE, v1.y * QSCALE);
                    size_t a0 = (((size_t)((r0 >> 9) * 16 + hh)) * T + (r0 & 511)) * HD + dd;
                    size_t a1 = (((size_t)((r1 >> 9) * 16 + hh)) * T + (r1 & 511)) * HD + dd;
                    *(__half2*)(pq + a0) = q0;
                    *(__half2*)(pq + a1) = q1;
                } else {
                    __half* dst = (seg == 0) ? pk : pv;
                    __half2 h0 = __floats2half2_rn(v0.x, v0.y);
                    __half2 h1 = __floats2half2_rn(v1.x, v1.y);
                    size_t a0 = (((size_t)((r0 >> 9) * 16 + hh)) * ST + S + (r0 & 511)) * HD + dd;
                    size_t a1 = (((size_t)((r1 >> 9) * 16 + hh)) * ST + S + (r1 & 511)) * HD + dd;
                    *(__half2*)(dst + a0) = h0;
                    *(__half2*)(dst + a1) = h1;
                }
            }
        }
    }
}

// ---------------------------------------------------------------------------
// Flash attention — EXACT R13 config (4 warps x 32 query rows, lb(128,3)):
// R14's 8x16 re-warping doubled per-CTA B-fragment ldsm traffic (L1 33->60%)
// and regressed; M=32/warp maximizes smem arithmetic intensity.
// ---------------------------------------------------------------------------
#define PROW 144
#define CH 128
#define NCHU (ST / CH)
#define KTILE (CH * PROW)
#define ATTN_SMEM (4 * KTILE)

__global__ __launch_bounds__(128, 3)
void attn_h(const __half* __restrict__ kh, const __half* __restrict__ vh,
            const __half* __restrict__ qh)
{
    extern __shared__ char smc[];
    const int tid  = threadIdx.x;
    const int wid  = tid >> 5;
    const int lane = tid & 31;
    const int t0 = blockIdx.x * 128;
    const int h  = blockIdx.y;
    const int b  = blockIdx.z;

    const uint32_t Sb  = smem_u32(smc);
    const uint32_t Kb0 = Sb;
    const uint32_t Vb0 = Sb + 2 * KTILE;

    const __half* khp = kh + ((size_t)(b * NH + h)) * ST * HD;
    const __half* vhp = vh + ((size_t)(b * NH + h)) * ST * HD;
    const __half* qhp = qh + ((size_t)(b * NH + h)) * T * HD + (size_t)t0 * HD;

    // ---- init V pad columns: col 64 = 1.0, cols 65-71 = 0 (both buffers) ----
    {
        uint4 ones = make_uint4(0x00003C00u, 0u, 0u, 0u);
#pragma unroll
        for (int rr = 0; rr < 2; rr++) {
            int r = tid + rr * 128;
            uint32_t addr = Vb0 + (uint32_t)((r >> 7) * KTILE + (r & 127) * PROW + 128);
            asm volatile("st.shared.v4.b32 [%0], {%1,%2,%3,%4};"
                         :: "r"(addr), "r"(ones.x), "r"(ones.y), "r"(ones.z), "r"(ones.w));
        }
    }

    // ---- stage Q into K buffer 0 ----
#pragma unroll
    for (int u = 0; u < 8; u++) {
        int idx = tid + u * 128;
        int r = idx >> 3, c8 = idx & 7;
        cp_async16_cg(Kb0 + (uint32_t)(r * PROW + c8 * 16), qhp + (size_t)r * HD + c8 * 8);
    }
    CP_COMMIT();
    CP_WAIT(0);
    __syncthreads();

    uint32_t qf[2][4][4];
#pragma unroll
    for (int tm = 0; tm < 2; tm++) {
        uint32_t aoff = (uint32_t)((wid * 32 + tm * 16 + (lane & 15)) * PROW + (lane >> 4) * 16);
#pragma unroll
        for (int ks = 0; ks < 4; ks++)
            ldsm_x4(qf[tm][ks][0], qf[tm][ks][1], qf[tm][ks][2], qf[tm][ks][3],
                    Sb + aoff + ks * 32);
    }
    __syncthreads();

    uint32_t koff4[4];
#pragma unroll
    for (int p = 0; p < 4; p++)
        koff4[p] = (uint32_t)((p * 16 + (lane & 7) + ((lane >> 4) & 1) * 8) * PROW
                              + ((lane >> 3) & 1) * 16);
    const uint32_t voff4 = (uint32_t)(((lane & 7) + ((lane >> 3) & 1) * 8) * PROW
                                      + ((lane >> 4) & 1) * 16);

    float O[2][8][4];
#pragma unroll
    for (int tm = 0; tm < 2; tm++)
#pragma unroll
        for (int tn = 0; tn < 8; tn++)
#pragma unroll
            for (int v = 0; v < 4; v++) O[tm][tn][v] = 0.f;
    float Ol[2][4];
#pragma unroll
    for (int tm = 0; tm < 2; tm++)
#pragma unroll
        for (int v = 0; v < 4; v++) Ol[tm][v] = 0.f;

#pragma unroll
    for (int u = 0; u < 8; u++) {
        int idx = tid + u * 128;
        int r = idx >> 3, c8 = idx & 7;
        uint32_t doff = (uint32_t)(r * PROW + c8 * 16);
        cp_async16_cg(Kb0 + doff, khp + (size_t)r * HD + c8 * 8);
        cp_async16_cg(Vb0 + doff, vhp + (size_t)r * HD + c8 * 8);
    }
    CP_COMMIT();

    for (int i = 0; i < NCHU; i++) {
        if (i < NCHU - 1) {
            __syncthreads();
            const int buf = (i + 1) & 1;
            const uint32_t kb = Kb0 + buf * KTILE;
            const uint32_t vb = Vb0 + buf * KTILE;
            const size_t s0n = (size_t)(i + 1) * CH;
#pragma unroll
            for (int u = 0; u < 8; u++) {
                int idx = tid + u * 128;
                int r = idx >> 3, c8 = idx & 7;
                uint32_t doff = (uint32_t)(r * PROW + c8 * 16);
                cp_async16_cg(kb + doff, khp + (s0n + r) * HD + c8 * 8);
                cp_async16_cg(vb + doff, vhp + (s0n + r) * HD + c8 * 8);
            }
            CP_COMMIT();
            CP_WAIT(1);
        } else {
            CP_WAIT(0);
        }
        __syncthreads();

        const uint32_t kbb = Kb0 + (i & 1) * KTILE;
        const uint32_t vbb = Vb0 + (i & 1) * KTILE;

#pragma unroll
        for (int sub = 0; sub < 2; sub++) {
            const uint32_t kb = kbb + sub * (64 * PROW);
            const uint32_t vb = vbb + sub * (64 * PROW);

            float sf[2][8][4];
#pragma unroll
            for (int tm = 0; tm < 2; tm++)
#pragma unroll
                for (int tn = 0; tn < 8; tn++)
#pragma unroll
                    for (int v = 0; v < 4; v++) sf[tm][tn][v] = 0.f;
#pragma unroll
            for (int ks = 0; ks < 4; ks++) {
                uint32_t bf[8][2];
#pragma unroll
                for (int p = 0; p < 4; p++)
                    ldsm_x4(bf[2 * p][0], bf[2 * p][1], bf[2 * p + 1][0], bf[2 * p + 1][1],
                            kb + koff4[p] + ks * 32);
#pragma unroll
                for (int tm = 0; tm < 2; tm++)
#pragma unroll
                    for (int tn = 0; tn < 8; tn++)
                        mma_f16(sf[tm][tn], qf[tm][ks], bf[tn][0], bf[tn][1]);
            }

            uint32_t ph[2][8][2];
#pragma unroll
            for (int tm = 0; tm < 2; tm++) {
#pragma unroll
                for (int tn = 0; tn < 8; tn++) {
                    __half2 hlo = __floats2half2_rn(sf[tm][tn][0], sf[tm][tn][1]);
                    __half2 hhi = __floats2half2_rn(sf[tm][tn][2], sf[tm][tn][3]);
                    ph[tm][tn][0] = ex2_h2(*(uint32_t*)&hlo);
                    ph[tm][tn][1] = ex2_h2(*(uint32_t*)&hhi);
                }
            }

#pragma unroll
            for (int ks = 0; ks < 4; ks++) {
                uint32_t bv[8][2];
#pragma unroll
                for (int p = 0; p < 4; p++)
                    ldsm_x4_trans(bv[2 * p][0], bv[2 * p][1], bv[2 * p + 1][0], bv[2 * p + 1][1],
                                  vb + voff4 + ks * (16 * PROW) + p * 32);
                uint32_t bl0, bl1;
                ldsm_x2_trans(bl0, bl1, vb + voff4 + ks * (16 * PROW) + 128);
#pragma unroll
                for (int tm = 0; tm < 2; tm++) {
                    uint32_t a[4] = { ph[tm][2 * ks][0],     ph[tm][2 * ks][1],
                                      ph[tm][2 * ks + 1][0], ph[tm][2 * ks + 1][1] };
#pragma unroll
                    for (int tn = 0; tn < 8; tn++)
                        mma_f16(O[tm][tn], a, bv[tn][0], bv[tn][1]);
                    mma_f16(Ol[tm], a, bl0, bl1);
                }
            }
        }
    }

    const int rowq = lane >> 2;
#pragma unroll
    for (int tm = 0; tm < 2; tm++) {
        const float lv0 = __shfl_sync(0xFFFFFFFFu, Ol[tm][0], lane & 28);
        const float lv1 = __shfl_sync(0xFFFFFFFFu, Ol[tm][2], lane & 28);
        const float inv0 = 1.f / lv0;
        const float inv1 = 1.f / lv1;
        const int ra = t0 + wid * 32 + tm * 16 + rowq;
        const int ca = h * HD + (lane & 3) * 2;
        __half* o0 = g_wvh + (size_t)(b * T + ra) * NS + ca;
        __half* o1 = o0 + (size_t)8 * NS;
#pragma unroll
        for (int tn = 0; tn < 8; tn++) {
            *(__half2*)(o0 + tn * 8) = __floats2half2_rn(O[tm][tn][0] * inv0, O[tm][tn][1] * inv0);
            *(__half2*)(o1 + tn * 8) = __floats2half2_rn(O[tm][tn][2] * inv1, O[tm][tn][3] * inv1);
        }
    }
}

// ---------------------------------------------------------------------------
// kernel_launch
// ---------------------------------------------------------------------------
extern "C" void kernel_launch(void* const* d_in, const int* in_sizes, int n_in,
                              void* d_out, int out_size)
{
    const float* x  = (const float*)d_in[0];
    const float* kv = (const float*)d_in[1];
    const float* Wq = (const float*)d_in[3];
    const float* bq = (const float*)d_in[4];
    const float* Wk = (const float*)d_in[5];
    const float* Wv = (const float*)d_in[6];
    const float* bv = (const float*)d_in[7];
    const float* Wo = (const float*)d_in[8];
    const float* bo = (const float*)d_in[9];

    float* out  = (float*)d_out;
    float* keyo = out + (size_t)BT * NS;
    float* valo = keyo + (size_t)BT * NS;

    __half *xh, *wvh, *wth, *khb, *vhb, *qhb;
    cudaGetSymbolAddress((void**)&xh, g_xh);
    cudaGetSymbolAddress((void**)&wvh, g_wvh);
    cudaGetSymbolAddress((void**)&wth, g_wth);
    cudaGetSymbolAddress((void**)&khb, g_kh);
    cudaGetSymbolAddress((void**)&vhb, g_vh);
    cudaGetSymbolAddress((void**)&qhb, g_qh);
    __half* wtO = wth + (size_t)3 * NS * NS;

    cudaFuncSetAttribute(gemm_h3, cudaFuncAttributeMaxDynamicSharedMemorySize, GSM_TOTAL);
    cudaFuncSetAttribute(attn_h, cudaFuncAttributeMaxDynamicSharedMemorySize, ATTN_SMEM);

    const int n4 = BT * NS / 4;
    cvt_xh<<<(n4 + 255) / 256, 256>>>(x, xh, n4);
    dim3 tb(32, 8), tg(32, 32, 4);
    transpose_cvt_h<<<tg, tb>>>(Wk, Wv, Wq, Wo, wth);

    // fused QKV projection + KV-cache pack filler CTAs
    dim3 gq(GEMM_XBLKS + PACK_XBLKS, 32);
    gemm_h3<<<gq, 256, GSM_TOTAL>>>(xh, wth, nullptr, bv, bq,
                                    keyo, valo, nullptr, khb, vhb, qhb, kv);

    dim3 ag(T / 128, NH, B);
    attn_h<<<ag, 128, ATTN_SMEM>>>(khb, vhb, qhb);

    dim3 go(8, 32);
    gemm_h3<<<go, 256, GSM_TOTAL>>>(wvh, wtO, bo, bo, bo,
                                    out, out, out, nullptr, nullptr, nullptr, nullptr);
}

// round 16
// speedup vs baseline: 1.1261x; 1.1261x over previous
#include <cuda_runtime.h>
#include <cuda_fp16.h>
#include <math_constants.h>
#include <cstdint>

#define B 8
#define T 512
#define S 2048
#define L 4
#define NS 1024
#define NH 16
#define HD 64
#define ST (S + T)
#define BT (B * T)

#define QSCALE 0.18033688f   // HD^-0.5 * log2(e)

// Scratch (no allocations allowed)
__device__ __half g_wvh[BT * NS];                   // attention output (half)
__device__ __half g_xh[BT * NS];                    // x as half
__device__ __half g_wth[4 * NS * NS];               // transposed half weights [N][K]
__device__ __half g_kh[(size_t)B * NH * ST * HD];   // packed K [b][h][s][d]
__device__ __half g_vh[(size_t)B * NH * ST * HD];   // packed V [b][h][s][d]
__device__ __half g_qh[(size_t)B * NH * T * HD];    // packed scaled Q [b][h][t][d]

// ---------------------------------------------------------------------------
// helpers
// ---------------------------------------------------------------------------
__device__ __forceinline__ uint32_t smem_u32(const void* p) {
    uint32_t a;
    asm("{ .reg .u64 t; cvta.to.shared.u64 t, %1; cvt.u32.u64 %0, t; }" : "=r"(a) : "l"(p));
    return a;
}
__device__ __forceinline__ void cp_async16_ca(uint32_t saddr, const void* gaddr) {
    asm volatile("cp.async.ca.shared.global [%0], [%1], 16;" :: "r"(saddr), "l"(gaddr));
}
__device__ __forceinline__ void cp_async16_cg(uint32_t saddr, const void* gaddr) {
    asm volatile("cp.async.cg.shared.global [%0], [%1], 16;" :: "r"(saddr), "l"(gaddr));
}
#define CP_COMMIT() asm volatile("cp.async.commit_group;" ::: "memory")
#define CP_WAIT(n)  asm volatile("cp.async.wait_group %0;" :: "n"(n) : "memory")

__device__ __forceinline__ void ldsm_x4(uint32_t& r0, uint32_t& r1, uint32_t& r2, uint32_t& r3,
                                        uint32_t addr) {
    asm volatile("ldmatrix.sync.aligned.m8n8.x4.shared.b16 {%0,%1,%2,%3}, [%4];"
                 : "=r"(r0), "=r"(r1), "=r"(r2), "=r"(r3) : "r"(addr));
}
__device__ __forceinline__ void ldsm_x4_trans(uint32_t& r0, uint32_t& r1, uint32_t& r2, uint32_t& r3,
                                              uint32_t addr) {
    asm volatile("ldmatrix.sync.aligned.m8n8.x4.trans.shared.b16 {%0,%1,%2,%3}, [%4];"
                 : "=r"(r0), "=r"(r1), "=r"(r2), "=r"(r3) : "r"(addr));
}
__device__ __forceinline__ void ldsm_x2_trans(uint32_t& r0, uint32_t& r1, uint32_t addr) {
    asm volatile("ldmatrix.sync.aligned.m8n8.x2.trans.shared.b16 {%0,%1}, [%2];"
                 : "=r"(r0), "=r"(r1) : "r"(addr));
}
__device__ __forceinline__ void mma_f16(float* c, const uint32_t* a, uint32_t b0, uint32_t b1) {
    asm volatile(
        "mma.sync.aligned.m16n8k16.row.col.f32.f16.f16.f32 "
        "{%0,%1,%2,%3}, {%4,%5,%6,%7}, {%8,%9}, {%0,%1,%2,%3};"
        : "+f"(c[0]), "+f"(c[1]), "+f"(c[2]), "+f"(c[3])
        : "r"(a[0]), "r"(a[1]), "r"(a[2]), "r"(a[3]), "r"(b0), "r"(b1));
}
__device__ __forceinline__ uint32_t ex2_h2(uint32_t h) {
    uint32_t r; asm("ex2.approx.f16x2 %0, %1;" : "=r"(r) : "r"(h)); return r;
}

// ---------------------------------------------------------------------------
// Weight transposes + x conversion in ONE launch.
// z in [0,4): dst[z][n][k] = half(src_z[k][n]).  z == 4: xh = half(x).
// ---------------------------------------------------------------------------
__global__ __launch_bounds__(256)
void prep_h(const float* __restrict__ W0, const float* __restrict__ W1,
            const float* __restrict__ W2, const float* __restrict__ W3,
            __half* __restrict__ dst,
            const float* __restrict__ x, __half* __restrict__ xh)
{
    const int z = blockIdx.z;
    if (z == 4) {
        // x: BT*NS floats = 1,048,576 float4; 1024 blocks x 256 thr x 4
        int base = (blockIdx.y * 32 + blockIdx.x) * 1024 + threadIdx.x
                 + threadIdx.y * 32;
#pragma unroll
        for (int u = 0; u < 4; u++) {
            int i = base + u * 256;
            float4 v = ((const float4*)x)[i];
            __half2 h0 = __floats2half2_rn(v.x, v.y);
            __half2 h1 = __floats2half2_rn(v.z, v.w);
            ((uint2*)xh)[i] = make_uint2(*(uint32_t*)&h0, *(uint32_t*)&h1);
        }
        return;
    }

    __shared__ float t[32][33];
    const int tx = threadIdx.x, ty = threadIdx.y;
    const int bx = blockIdx.x * 32;
    const int by = blockIdx.y * 32;
    const float* src = (z == 0) ? W0 : (z == 1) ? W1 : (z == 2) ? W2 : W3;
    __half* out = dst + (size_t)z * NS * NS;
#pragma unroll
    for (int i = 0; i < 32; i += 8)
        t[ty + i][tx] = src[(size_t)(by + ty + i) * NS + bx + tx];
    __syncthreads();
#pragma unroll
    for (int i = 0; i < 32; i += 8)
        out[(size_t)(bx + ty + i) * NS + by + tx] = __float2half_rn(t[tx][ty + i]);
}

// ---------------------------------------------------------------------------
// fp16 mma GEMM (EXACT R13 config: 2-stage, 73.7 KB smem, .ca, lb(256,2)),
// 3-segment output, FUSED KV-cache pack filler CTAs.
// ---------------------------------------------------------------------------
#define PHG 72
#define PROWG (PHG * 2)                 // 144 B
#define GTILE_B (128 * PROWG)           // 18432
#define GSTAGE_B (2 * GTILE_B)          // 36864
#define GEMM_SMEM (2 * GSTAGE_B)        // 73728
#define GEMM_XBLKS 24
#define PACK_XBLKS 64                   // 64*32 = 2048 pack CTAs

__global__ __launch_bounds__(256, 2)
void gemm_h3(const __half* __restrict__ A, const __half* __restrict__ Bt,
             const float* __restrict__ b0, const float* __restrict__ b1,
             const float* __restrict__ b2,
             float* __restrict__ Y0, float* __restrict__ Y1, float* __restrict__ Y2,
             __half* __restrict__ pk, __half* __restrict__ pv, __half* __restrict__ pq,
             const float* __restrict__ cache)
{
    extern __shared__ char smc[];
    __shared__ float s_bias[128];

    const uint32_t tid  = threadIdx.x;
    const bool isQKV = (pq != nullptr);

    if (isQKV && blockIdx.x >= GEMM_XBLKS) {
        const int pb = (blockIdx.x - GEMM_XBLKS) * 32 + blockIdx.y;   // 0..2047
#pragma unroll
        for (int u = 0; u < 8; u++) {
            int idx = pb * 2048 + u * 256 + (int)tid;
            int d4 = idx & 15;
            int t  = idx >> 4;
            int s  = t % S;
            int bh = t / S;
            int b = bh >> 4, h = bh & 15;
            const float* base = cache + (size_t)b * (L * 2 * S * NS)
                              + (size_t)s * NS + h * HD + d4 * 4;
            float4 k4 = *(const float4*)base;
            float4 v4 = *(const float4*)(base + (size_t)S * NS);
            __half2 k0 = __floats2half2_rn(k4.x, k4.y);
            __half2 k1 = __floats2half2_rn(k4.z, k4.w);
            __half2 v0 = __floats2half2_rn(v4.x, v4.y);
            __half2 v1 = __floats2half2_rn(v4.z, v4.w);
            size_t oidx = ((size_t)bh * ST + s) * 16 + d4;
            ((uint2*)pk)[oidx] = make_uint2(*(uint32_t*)&k0, *(uint32_t*)&k1);
            ((uint2*)pv)[oidx] = make_uint2(*(uint32_t*)&v0, *(uint32_t*)&v1);
        }
        return;
    }

    const uint32_t wid  = tid >> 5;
    const uint32_t lane = tid & 31;
    const int row0 = blockIdx.y * 128;
    const int seg  = blockIdx.x >> 3;
    const int ycol0 = (blockIdx.x & 7) * 128;

    const float* bias = (seg == 0) ? b0 : (seg == 1) ? b1 : b2;
    float* Y = (seg == 0) ? Y0 : (seg == 1) ? Y1 : Y2;

    if (tid < 32) {
        float4 v = bias ? *(const float4*)&bias[ycol0 + tid * 4]
                        : make_float4(0.f, 0.f, 0.f, 0.f);
        *(float4*)&s_bias[tid * 4] = v;
    }

    const uint32_t smBase = smem_u32(smc);
    const __half* Ab = A  + (size_t)row0 * NS;
    const __half* Bb = Bt + (size_t)blockIdx.x * 128 * NS;

    uint32_t stOff[4];
    const __half* gA[4];
    const __half* gB[4];
#pragma unroll
    for (int u = 0; u < 4; u++) {
        int idx = (int)tid + u * 256;
        int r = idx >> 3, c8 = idx & 7;
        stOff[u] = (uint32_t)(r * PROWG + c8 * 16);
        gA[u] = Ab + (size_t)r * NS + c8 * 8;
        gB[u] = Bb + (size_t)r * NS + c8 * 8;
    }

    const uint32_t wm = wid >> 2;
    const uint32_t wn = wid & 3;
    uint32_t offA[4], offB[2];
#pragma unroll
    for (int tm = 0; tm < 4; tm++)
        offA[tm] = (uint32_t)((wm * 64 + tm * 16 + (lane & 15)) * PROWG + (lane >> 4) * 16);
#pragma unroll
    for (int p = 0; p < 2; p++)
        offB[p] = (uint32_t)((wn * 32 + p * 16 + (lane & 7) + ((lane >> 4) & 1) * 8) * PROWG
                             + ((lane >> 3) & 1) * 16 + GTILE_B);

    float acc[4][4][4];
#pragma unroll
    for (int i = 0; i < 4; i++)
#pragma unroll
        for (int j = 0; j < 4; j++)
#pragma unroll
            for (int v = 0; v < 4; v++) acc[i][j][v] = 0.f;

#pragma unroll
    for (int u = 0; u < 4; u++) {
        cp_async16_ca(smBase + stOff[u], gA[u]);
        cp_async16_ca(smBase + GTILE_B + stOff[u], gB[u]);
    }
    CP_COMMIT();

    for (int i = 0; i < 16; i++) {
        if (i < 15) {
            const uint32_t st = smBase + ((i + 1) & 1) * GSTAGE_B;
            const int koff = (i + 1) * 64;
#pragma unroll
            for (int u = 0; u < 4; u++) {
                cp_async16_ca(st + stOff[u], gA[u] + koff);
                cp_async16_ca(st + GTILE_B + stOff[u], gB[u] + koff);
            }
            CP_COMMIT();
            CP_WAIT(1);
        } else {
            CP_WAIT(0);
        }
        __syncthreads();

        const uint32_t stage = smBase + (i & 1) * GSTAGE_B;
#pragma unroll
        for (int ks = 0; ks < 4; ks++) {
            uint32_t af[4][4], bf[4][2];
#pragma unroll
            for (int tm = 0; tm < 4; tm++)
                ldsm_x4(af[tm][0], af[tm][1], af[tm][2], af[tm][3],
                        stage + offA[tm] + ks * 32);
#pragma unroll
            for (int p = 0; p < 2; p++)
                ldsm_x4(bf[2 * p][0], bf[2 * p][1], bf[2 * p + 1][0], bf[2 * p + 1][1],
                        stage + offB[p] + ks * 32);
#pragma unroll
            for (int tm = 0; tm < 4; tm++)
#pragma unroll
                for (int tn = 0; tn < 4; tn++)
                    mma_f16(acc[tm][tn], af[tm], bf[tn][0], bf[tn][1]);
        }
        __syncthreads();
    }

    const int rbase = row0 + (int)wm * 64 + (int)(lane >> 2);
    const int cbase = ycol0 + (int)wn * 32 + (int)(lane & 3) * 2;
    const int csb   = (int)wn * 32 + (int)(lane & 3) * 2;

#pragma unroll
    for (int tm = 0; tm < 4; tm++) {
#pragma unroll
        for (int tn = 0; tn < 4; tn++) {
            float b0v = s_bias[csb + tn * 8];
            float b1v = s_bias[csb + tn * 8 + 1];
            float2 v0 = make_float2(acc[tm][tn][0] + b0v, acc[tm][tn][1] + b1v);
            float2 v1 = make_float2(acc[tm][tn][2] + b0v, acc[tm][tn][3] + b1v);
            const int r0 = rbase + tm * 16;
            const int r1 = r0 + 8;
            const int c  = cbase + tn * 8;

            if (!isQKV || seg < 2) {
                *(float2*)(Y + (size_t)r0 * NS + c) = v0;
                *(float2*)(Y + (size_t)r1 * NS + c) = v1;
            }
            if (isQKV) {
                const int hh = c >> 6, dd = c & 63;
                if (seg == 2) {
                    __half2 q0 = __floats2half2_rn(v0.x * QSCALE, v0.y * QSCALE);
                    __half2 q1 = __floats2half2_rn(v1.x * QSCALE, v1.y * QSCALE);
                    size_t a0 = (((size_t)((r0 >> 9) * 16 + hh)) * T + (r0 & 511)) * HD + dd;
                    size_t a1 = (((size_t)((r1 >> 9) * 16 + hh)) * T + (r1 & 511)) * HD + dd;
                    *(__half2*)(pq + a0) = q0;
                    *(__half2*)(pq + a1) = q1;
                } else {
                    __half* dst = (seg == 0) ? pk : pv;
                    __half2 h0 = __floats2half2_rn(v0.x, v0.y);
                    __half2 h1 = __floats2half2_rn(v1.x, v1.y);
                    size_t a0 = (((size_t)((r0 >> 9) * 16 + hh)) * ST + S + (r0 & 511)) * HD + dd;
                    size_t a1 = (((size_t)((r1 >> 9) * 16 + hh)) * ST + S + (r1 & 511)) * HD + dd;
                    *(__half2*)(dst + a0) = h0;
                    *(__half2*)(dst + a1) = h1;
                }
            }
        }
    }
}

// ---------------------------------------------------------------------------
// Flash attention — R13 config (4 warps x 32 query rows, lb(128,3)) with
// R16 prologue overlap: chunk-0 K/V loads issued BEFORE Q staging; Q stages
// into K buffer 1 (first overwritten at chunk 1, behind the loop's sync).
// ---------------------------------------------------------------------------
#define PROW 144
#define CH 128
#define NCHU (ST / CH)
#define KTILE (CH * PROW)
#define ATTN_SMEM (4 * KTILE)

__global__ __launch_bounds__(128, 3)
void attn_h(const __half* __restrict__ kh, const __half* __restrict__ vh,
            const __half* __restrict__ qh)
{
    extern __shared__ char smc[];
    const int tid  = threadIdx.x;
    const int wid  = tid >> 5;
    const int lane = tid & 31;
    const int t0 = blockIdx.x * 128;
    const int h  = blockIdx.y;
    const int b  = blockIdx.z;

    const uint32_t Sb  = smem_u32(smc);
    const uint32_t Kb0 = Sb;
    const uint32_t Qb  = Sb + KTILE;          // K buffer 1 (transient Q home)
    const uint32_t Vb0 = Sb + 2 * KTILE;

    const __half* khp = kh + ((size_t)(b * NH + h)) * ST * HD;
    const __half* vhp = vh + ((size_t)(b * NH + h)) * ST * HD;
    const __half* qhp = qh + ((size_t)(b * NH + h)) * T * HD + (size_t)t0 * HD;

    // ---- init V pad columns: col 64 = 1.0, cols 65-71 = 0 (both buffers) ----
    {
        uint4 ones = make_uint4(0x00003C00u, 0u, 0u, 0u);
#pragma unroll
        for (int rr = 0; rr < 2; rr++) {
            int r = tid + rr * 128;
            uint32_t addr = Vb0 + (uint32_t)((r >> 7) * KTILE + (r & 127) * PROW + 128);
            asm volatile("st.shared.v4.b32 [%0], {%1,%2,%3,%4};"
                         :: "r"(addr), "r"(ones.x), "r"(ones.y), "r"(ones.z), "r"(ones.w));
        }
    }

    // ---- issue chunk-0 K/V loads FIRST (overlap with Q staging) ----
#pragma unroll
    for (int u = 0; u < 8; u++) {
        int idx = tid + u * 128;
        int r = idx >> 3, c8 = idx & 7;
        uint32_t doff = (uint32_t)(r * PROW + c8 * 16);
        cp_async16_cg(Kb0 + doff, khp + (size_t)r * HD + c8 * 8);
        cp_async16_cg(Vb0 + doff, vhp + (size_t)r * HD + c8 * 8);
    }
    CP_COMMIT();

    // ---- stage Q into K buffer 1 ----
#pragma unroll
    for (int u = 0; u < 8; u++) {
        int idx = tid + u * 128;
        int r = idx >> 3, c8 = idx & 7;
        cp_async16_cg(Qb + (uint32_t)(r * PROW + c8 * 16), qhp + (size_t)r * HD + c8 * 8);
    }
    CP_COMMIT();
    CP_WAIT(0);
    __syncthreads();

    uint32_t qf[2][4][4];
#pragma unroll
    for (int tm = 0; tm < 2; tm++) {
        uint32_t aoff = (uint32_t)((wid * 32 + tm * 16 + (lane & 15)) * PROW + (lane >> 4) * 16);
#pragma unroll
        for (int ks = 0; ks < 4; ks++)
            ldsm_x4(qf[tm][ks][0], qf[tm][ks][1], qf[tm][ks][2], qf[tm][ks][3],
                    Qb + aoff + ks * 32);
    }
    // no sync needed: main loop's first __syncthreads (before chunk-1 staging
    // into Qb's region) orders all Q reads before the overwrite.

    uint32_t koff4[4];
#pragma unroll
    for (int p = 0; p < 4; p++)
        koff4[p] = (uint32_t)((p * 16 + (lane & 7) + ((lane >> 4) & 1) * 8) * PROW
                              + ((lane >> 3) & 1) * 16);
    const uint32_t voff4 = (uint32_t)(((lane & 7) + ((lane >> 3) & 1) * 8) * PROW
                                      + ((lane >> 4) & 1) * 16);

    float O[2][8][4];
#pragma unroll
    for (int tm = 0; tm < 2; tm++)
#pragma unroll
        for (int tn = 0; tn < 8; tn++)
#pragma unroll
            for (int v = 0; v < 4; v++) O[tm][tn][v] = 0.f;
    float Ol[2][4];
#pragma unroll
    for (int tm = 0; tm < 2; tm++)
#pragma unroll
        for (int v = 0; v < 4; v++) Ol[tm][v] = 0.f;

    for (int i = 0; i < NCHU; i++) {
        if (i < NCHU - 1) {
            __syncthreads();
            const int buf = (i + 1) & 1;
            const uint32_t kb = Kb0 + buf * KTILE;
            const uint32_t vb = Vb0 + buf * KTILE;
            const size_t s0n = (size_t)(i + 1) * CH;
#pragma unroll
            for (int u = 0; u < 8; u++) {
                int idx = tid + u * 128;
                int r = idx >> 3, c8 = idx & 7;
                uint32_t doff = (uint32_t)(r * PROW + c8 * 16);
                cp_async16_cg(kb + doff, khp + (s0n + r) * HD + c8 * 8);
                cp_async16_cg(vb + doff, vhp + (s0n + r) * HD + c8 * 8);
            }
            CP_COMMIT();
            CP_WAIT(1);
        } else {
            CP_WAIT(0);
        }
        __syncthreads();

        const uint32_t kbb = Kb0 + (i & 1) * KTILE;
        const uint32_t vbb = Vb0 + (i & 1) * KTILE;

#pragma unroll
        for (int sub = 0; sub < 2; sub++) {
            const uint32_t kb = kbb + sub * (64 * PROW);
            const uint32_t vb = vbb + sub * (64 * PROW);

            float sf[2][8][4];
#pragma unroll
            for (int tm = 0; tm < 2; tm++)
#pragma unroll
                for (int tn = 0; tn < 8; tn++)
#pragma unroll
                    for (int v = 0; v < 4; v++) sf[tm][tn][v] = 0.f;
#pragma unroll
            for (int ks = 0; ks < 4; ks++) {
                uint32_t bf[8][2];
#pragma unroll
                for (int p = 0; p < 4; p++)
                    ldsm_x4(bf[2 * p][0], bf[2 * p][1], bf[2 * p + 1][0], bf[2 * p + 1][1],
                            kb + koff4[p] + ks * 32);
#pragma unroll
                for (int tm = 0; tm < 2; tm++)
#pragma unroll
                    for (int tn = 0; tn < 8; tn++)
                        mma_f16(sf[tm][tn], qf[tm][ks], bf[tn][0], bf[tn][1]);
            }

            uint32_t ph[2][8][2];
#pragma unroll
            for (int tm = 0; tm < 2; tm++) {
#pragma unroll
                for (int tn = 0; tn < 8; tn++) {
                    __half2 hlo = __floats2half2_rn(sf[tm][tn][0], sf[tm][tn][1]);
                    __half2 hhi = __floats2half2_rn(sf[tm][tn][2], sf[tm][tn][3]);
                    ph[tm][tn][0] = ex2_h2(*(uint32_t*)&hlo);
                    ph[tm][tn][1] = ex2_h2(*(uint32_t*)&hhi);
                }
            }

#pragma unroll
            for (int ks = 0; ks < 4; ks++) {
                uint32_t bv[8][2];
#pragma unroll
                for (int p = 0; p < 4; p++)
                    ldsm_x4_trans(bv[2 * p][0], bv[2 * p][1], bv[2 * p + 1][0], bv[2 * p + 1][1],
                                  vb + voff4 + ks * (16 * PROW) + p * 32);
                uint32_t bl0, bl1;
                ldsm_x2_trans(bl0, bl1, vb + voff4 + ks * (16 * PROW) + 128);
#pragma unroll
                for (int tm = 0; tm < 2; tm++) {
                    uint32_t a[4] = { ph[tm][2 * ks][0],     ph[tm][2 * ks][1],
                                      ph[tm][2 * ks + 1][0], ph[tm][2 * ks + 1][1] };
#pragma unroll
                    for (int tn = 0; tn < 8; tn++)
                        mma_f16(O[tm][tn], a, bv[tn][0], bv[tn][1]);
                    mma_f16(Ol[tm], a, bl0, bl1);
                }
            }
        }
    }

    const int rowq = lane >> 2;
#pragma unroll
    for (int tm = 0; tm < 2; tm++) {
        const float lv0 = __shfl_sync(0xFFFFFFFFu, Ol[tm][0], lane & 28);
        const float lv1 = __shfl_sync(0xFFFFFFFFu, Ol[tm][2], lane & 28);
        const float inv0 = 1.f / lv0;
        const float inv1 = 1.f / lv1;
        const int ra = t0 + wid * 32 + tm * 16 + rowq;
        const int ca = h * HD + (lane & 3) * 2;
        __half* o0 = g_wvh + (size_t)(b * T + ra) * NS + ca;
        __half* o1 = o0 + (size_t)8 * NS;
#pragma unroll
        for (int tn = 0; tn < 8; tn++) {
            *(__half2*)(o0 + tn * 8) = __floats2half2_rn(O[tm][tn][0] * inv0, O[tm][tn][1] * inv0);
            *(__half2*)(o1 + tn * 8) = __floats2half2_rn(O[tm][tn][2] * inv1, O[tm][tn][3] * inv1);
        }
    }
}

// ---------------------------------------------------------------------------
// kernel_launch
// ---------------------------------------------------------------------------
extern "C" void kernel_launch(void* const* d_in, const int* in_sizes, int n_in,
                              void* d_out, int out_size)
{
    const float* x  = (const float*)d_in[0];
    const float* kv = (const float*)d_in[1];
    const float* Wq = (const float*)d_in[3];
    const float* bq = (const float*)d_in[4];
    const float* Wk = (const float*)d_in[5];
    const float* Wv = (const float*)d_in[6];
    const float* bv = (const float*)d_in[7];
    const float* Wo = (const float*)d_in[8];
    const float* bo = (const float*)d_in[9];

    float* out  = (float*)d_out;
    float* keyo = out + (size_t)BT * NS;
    float* valo = keyo + (size_t)BT * NS;

    __half *xh, *wvh, *wth, *khb, *vhb, *qhb;
    cudaGetSymbolAddress((void**)&xh, g_xh);
    cudaGetSymbolAddress((void**)&wvh, g_wvh);
    cudaGetSymbolAddress((void**)&wth, g_wth);
    cudaGetSymbolAddress((void**)&khb, g_kh);
    cudaGetSymbolAddress((void**)&vhb, g_vh);
    cudaGetSymbolAddress((void**)&qhb, g_qh);
    __half* wtO = wth + (size_t)3 * NS * NS;

    cudaFuncSetAttribute(gemm_h3, cudaFuncAttributeMaxDynamicSharedMemorySize, GEMM_SMEM);
    cudaFuncSetAttribute(attn_h, cudaFuncAttributeMaxDynamicSharedMemorySize, ATTN_SMEM);

    // prep: weight transposes + x conversion in one launch
    dim3 tb(32, 8), tg(32, 32, 5);
    prep_h<<<tg, tb>>>(Wk, Wv, Wq, Wo, wth, x, xh);

    // fused QKV projection + KV-cache pack filler CTAs
    dim3 gq(GEMM_XBLKS + PACK_XBLKS, 32);
    gemm_h3<<<gq, 256, GEMM_SMEM>>>(xh, wth, nullptr, bv, bq,
                                    keyo, valo, nullptr, khb, vhb, qhb, kv);

    dim3 ag(T / 128, NH, B);
    attn_h<<<ag, 128, ATTN_SMEM>>>(khb, vhb, qhb);

    dim3 go(8, 32);
    gemm_h3<<<go, 256, GEMM_SMEM>>>(wvh, wtO, bo, bo, bo,
                                    out, out, out, nullptr, nullptr, nullptr, nullptr);
}

// round 17
// speedup vs baseline: 1.1716x; 1.0404x over previous
#include <cuda_runtime.h>
#include <cuda_fp16.h>
#include <math_constants.h>
#include <cstdint>

#define B 8
#define T 512
#define S 2048
#define L 4
#define NS 1024
#define NH 16
#define HD 64
#define ST (S + T)
#define BT (B * T)
#define BHTD ((size_t)B * NH * T * HD)   // 4,194,304
#define BHT  (B * NH * T)                // 65,536

#define QSCALE 0.18033688f   // HD^-0.5 * log2(e)

// Scratch (no allocations allowed)
__device__ __half g_wvh[BT * NS];                   // attention output (half)
__device__ __half g_xh[BT * NS];                    // x as half
__device__ __half g_wth[4 * NS * NS];               // transposed half weights [N][K]
__device__ __half g_kh[(size_t)B * NH * ST * HD];   // packed K [b][h][s][d]
__device__ __half g_vh[(size_t)B * NH * ST * HD];   // packed V [b][h][s][d]
__device__ __half g_qh[(size_t)B * NH * T * HD];    // packed scaled Q [b][h][t][d]
__device__ float  g_po[2 * BHTD];                   // split-KV partial O (fp32)
__device__ float  g_pl[2 * BHT];                    // split-KV partial l

// ---------------------------------------------------------------------------
// helpers
// ---------------------------------------------------------------------------
__device__ __forceinline__ uint32_t smem_u32(const void* p) {
    uint32_t a;
    asm("{ .reg .u64 t; cvta.to.shared.u64 t, %1; cvt.u32.u64 %0, t; }" : "=r"(a) : "l"(p));
    return a;
}
__device__ __forceinline__ void cp_async16_ca(uint32_t saddr, const void* gaddr) {
    asm volatile("cp.async.ca.shared.global [%0], [%1], 16;" :: "r"(saddr), "l"(gaddr));
}
__device__ __forceinline__ void cp_async16_cg(uint32_t saddr, const void* gaddr) {
    asm volatile("cp.async.cg.shared.global [%0], [%1], 16;" :: "r"(saddr), "l"(gaddr));
}
#define CP_COMMIT() asm volatile("cp.async.commit_group;" ::: "memory")
#define CP_WAIT(n)  asm volatile("cp.async.wait_group %0;" :: "n"(n) : "memory")

__device__ __forceinline__ void ldsm_x4(uint32_t& r0, uint32_t& r1, uint32_t& r2, uint32_t& r3,
                                        uint32_t addr) {
    asm volatile("ldmatrix.sync.aligned.m8n8.x4.shared.b16 {%0,%1,%2,%3}, [%4];"
                 : "=r"(r0), "=r"(r1), "=r"(r2), "=r"(r3) : "r"(addr));
}
__device__ __forceinline__ void ldsm_x4_trans(uint32_t& r0, uint32_t& r1, uint32_t& r2, uint32_t& r3,
                                              uint32_t addr) {
    asm volatile("ldmatrix.sync.aligned.m8n8.x4.trans.shared.b16 {%0,%1,%2,%3}, [%4];"
                 : "=r"(r0), "=r"(r1), "=r"(r2), "=r"(r3) : "r"(addr));
}
__device__ __forceinline__ void ldsm_x2_trans(uint32_t& r0, uint32_t& r1, uint32_t addr) {
    asm volatile("ldmatrix.sync.aligned.m8n8.x2.trans.shared.b16 {%0,%1}, [%2];"
                 : "=r"(r0), "=r"(r1) : "r"(addr));
}
__device__ __forceinline__ void mma_f16(float* c, const uint32_t* a, uint32_t b0, uint32_t b1) {
    asm volatile(
        "mma.sync.aligned.m16n8k16.row.col.f32.f16.f16.f32 "
        "{%0,%1,%2,%3}, {%4,%5,%6,%7}, {%8,%9}, {%0,%1,%2,%3};"
        : "+f"(c[0]), "+f"(c[1]), "+f"(c[2]), "+f"(c[3])
        : "r"(a[0]), "r"(a[1]), "r"(a[2]), "r"(a[3]), "r"(b0), "r"(b1));
}
__device__ __forceinline__ uint32_t ex2_h2(uint32_t h) {
    uint32_t r; asm("ex2.approx.f16x2 %0, %1;" : "=r"(r) : "r"(h)); return r;
}

// ---------------------------------------------------------------------------
// Weight transposes + x conversion in ONE launch.
// ---------------------------------------------------------------------------
__global__ __launch_bounds__(256)
void prep_h(const float* __restrict__ W0, const float* __restrict__ W1,
            const float* __restrict__ W2, const float* __restrict__ W3,
            __half* __restrict__ dst,
            const float* __restrict__ x, __half* __restrict__ xh)
{
    const int z = blockIdx.z;
    if (z == 4) {
        int base = (blockIdx.y * 32 + blockIdx.x) * 1024 + threadIdx.x
                 + threadIdx.y * 32;
#pragma unroll
        for (int u = 0; u < 4; u++) {
            int i = base + u * 256;
            float4 v = ((const float4*)x)[i];
            __half2 h0 = __floats2half2_rn(v.x, v.y);
            __half2 h1 = __floats2half2_rn(v.z, v.w);
            ((uint2*)xh)[i] = make_uint2(*(uint32_t*)&h0, *(uint32_t*)&h1);
        }
        return;
    }

    __shared__ float t[32][33];
    const int tx = threadIdx.x, ty = threadIdx.y;
    const int bx = blockIdx.x * 32;
    const int by = blockIdx.y * 32;
    const float* src = (z == 0) ? W0 : (z == 1) ? W1 : (z == 2) ? W2 : W3;
    __half* out = dst + (size_t)z * NS * NS;
#pragma unroll
    for (int i = 0; i < 32; i += 8)
        t[ty + i][tx] = src[(size_t)(by + ty + i) * NS + bx + tx];
    __syncthreads();
#pragma unroll
    for (int i = 0; i < 32; i += 8)
        out[(size_t)(bx + ty + i) * NS + by + tx] = __float2half_rn(t[tx][ty + i]);
}

// ---------------------------------------------------------------------------
// fp16 mma GEMM (R13/R16 config), 3-segment output, FUSED KV-cache pack CTAs.
// ---------------------------------------------------------------------------
#define PHG 72
#define PROWG (PHG * 2)                 // 144 B
#define GTILE_B (128 * PROWG)           // 18432
#define GSTAGE_B (2 * GTILE_B)          // 36864
#define GEMM_SMEM (2 * GSTAGE_B)        // 73728
#define GEMM_XBLKS 24
#define PACK_XBLKS 64

__global__ __launch_bounds__(256, 2)
void gemm_h3(const __half* __restrict__ A, const __half* __restrict__ Bt,
             const float* __restrict__ b0, const float* __restrict__ b1,
             const float* __restrict__ b2,
             float* __restrict__ Y0, float* __restrict__ Y1, float* __restrict__ Y2,
             __half* __restrict__ pk, __half* __restrict__ pv, __half* __restrict__ pq,
             const float* __restrict__ cache)
{
    extern __shared__ char smc[];
    __shared__ float s_bias[128];

    const uint32_t tid  = threadIdx.x;
    const bool isQKV = (pq != nullptr);

    if (isQKV && blockIdx.x >= GEMM_XBLKS) {
        const int pb = (blockIdx.x - GEMM_XBLKS) * 32 + blockIdx.y;
#pragma unroll
        for (int u = 0; u < 8; u++) {
            int idx = pb * 2048 + u * 256 + (int)tid;
            int d4 = idx & 15;
            int t  = idx >> 4;
            int s  = t % S;
            int bh = t / S;
            int b = bh >> 4, h = bh & 15;
            const float* base = cache + (size_t)b * (L * 2 * S * NS)
                              + (size_t)s * NS + h * HD + d4 * 4;
            float4 k4 = *(const float4*)base;
            float4 v4 = *(const float4*)(base + (size_t)S * NS);
            __half2 k0 = __floats2half2_rn(k4.x, k4.y);
            __half2 k1 = __floats2half2_rn(k4.z, k4.w);
            __half2 v0 = __floats2half2_rn(v4.x, v4.y);
            __half2 v1 = __floats2half2_rn(v4.z, v4.w);
            size_t oidx = ((size_t)bh * ST + s) * 16 + d4;
            ((uint2*)pk)[oidx] = make_uint2(*(uint32_t*)&k0, *(uint32_t*)&k1);
            ((uint2*)pv)[oidx] = make_uint2(*(uint32_t*)&v0, *(uint32_t*)&v1);
        }
        return;
    }

    const uint32_t wid  = tid >> 5;
    const uint32_t lane = tid & 31;
    const int row0 = blockIdx.y * 128;
    const int seg  = blockIdx.x >> 3;
    const int ycol0 = (blockIdx.x & 7) * 128;

    const float* bias = (seg == 0) ? b0 : (seg == 1) ? b1 : b2;
    float* Y = (seg == 0) ? Y0 : (seg == 1) ? Y1 : Y2;

    if (tid < 32) {
        float4 v = bias ? *(const float4*)&bias[ycol0 + tid * 4]
                        : make_float4(0.f, 0.f, 0.f, 0.f);
        *(float4*)&s_bias[tid * 4] = v;
    }

    const uint32_t smBase = smem_u32(smc);
    const __half* Ab = A  + (size_t)row0 * NS;
    const __half* Bb = Bt + (size_t)blockIdx.x * 128 * NS;

    uint32_t stOff[4];
    const __half* gA[4];
    const __half* gB[4];
#pragma unroll
    for (int u = 0; u < 4; u++) {
        int idx = (int)tid + u * 256;
        int r = idx >> 3, c8 = idx & 7;
        stOff[u] = (uint32_t)(r * PROWG + c8 * 16);
        gA[u] = Ab + (size_t)r * NS + c8 * 8;
        gB[u] = Bb + (size_t)r * NS + c8 * 8;
    }

    const uint32_t wm = wid >> 2;
    const uint32_t wn = wid & 3;
    uint32_t offA[4], offB[2];
#pragma unroll
    for (int tm = 0; tm < 4; tm++)
        offA[tm] = (uint32_t)((wm * 64 + tm * 16 + (lane & 15)) * PROWG + (lane >> 4) * 16);
#pragma unroll
    for (int p = 0; p < 2; p++)
        offB[p] = (uint32_t)((wn * 32 + p * 16 + (lane & 7) + ((lane >> 4) & 1) * 8) * PROWG
                             + ((lane >> 3) & 1) * 16 + GTILE_B);

    float acc[4][4][4];
#pragma unroll
    for (int i = 0; i < 4; i++)
#pragma unroll
        for (int j = 0; j < 4; j++)
#pragma unroll
            for (int v = 0; v < 4; v++) acc[i][j][v] = 0.f;

#pragma unroll
    for (int u = 0; u < 4; u++) {
        cp_async16_ca(smBase + stOff[u], gA[u]);
        cp_async16_ca(smBase + GTILE_B + stOff[u], gB[u]);
    }
    CP_COMMIT();

    for (int i = 0; i < 16; i++) {
        if (i < 15) {
            const uint32_t st = smBase + ((i + 1) & 1) * GSTAGE_B;
            const int koff = (i + 1) * 64;
#pragma unroll
            for (int u = 0; u < 4; u++) {
                cp_async16_ca(st + stOff[u], gA[u] + koff);
                cp_async16_ca(st + GTILE_B + stOff[u], gB[u] + koff);
            }
            CP_COMMIT();
            CP_WAIT(1);
        } else {
            CP_WAIT(0);
        }
        __syncthreads();

        const uint32_t stage = smBase + (i & 1) * GSTAGE_B;
#pragma unroll
        for (int ks = 0; ks < 4; ks++) {
            uint32_t af[4][4], bf[4][2];
#pragma unroll
            for (int tm = 0; tm < 4; tm++)
                ldsm_x4(af[tm][0], af[tm][1], af[tm][2], af[tm][3],
                        stage + offA[tm] + ks * 32);
#pragma unroll
            for (int p = 0; p < 2; p++)
                ldsm_x4(bf[2 * p][0], bf[2 * p][1], bf[2 * p + 1][0], bf[2 * p + 1][1],
                        stage + offB[p] + ks * 32);
#pragma unroll
            for (int tm = 0; tm < 4; tm++)
#pragma unroll
                for (int tn = 0; tn < 4; tn++)
                    mma_f16(acc[tm][tn], af[tm], bf[tn][0], bf[tn][1]);
        }
        __syncthreads();
    }

    const int rbase = row0 + (int)wm * 64 + (int)(lane >> 2);
    const int cbase = ycol0 + (int)wn * 32 + (int)(lane & 3) * 2;
    const int csb   = (int)wn * 32 + (int)(lane & 3) * 2;

#pragma unroll
    for (int tm = 0; tm < 4; tm++) {
#pragma unroll
        for (int tn = 0; tn < 4; tn++) {
            float b0v = s_bias[csb + tn * 8];
            float b1v = s_bias[csb + tn * 8 + 1];
            float2 v0 = make_float2(acc[tm][tn][0] + b0v, acc[tm][tn][1] + b1v);
            float2 v1 = make_float2(acc[tm][tn][2] + b0v, acc[tm][tn][3] + b1v);
            const int r0 = rbase + tm * 16;
            const int r1 = r0 + 8;
            const int c  = cbase + tn * 8;

            if (!isQKV || seg < 2) {
                *(float2*)(Y + (size_t)r0 * NS + c) = v0;
                *(float2*)(Y + (size_t)r1 * NS + c) = v1;
            }
            if (isQKV) {
                const int hh = c >> 6, dd = c & 63;
                if (seg == 2) {
                    __half2 q0 = __floats2half2_rn(v0.x * QSCALE, v0.y * QSCALE);
                    __half2 q1 = __floats2half2_rn(v1.x * QSCALE, v1.y * QSCALE);
                    size_t a0 = (((size_t)((r0 >> 9) * 16 + hh)) * T + (r0 & 511)) * HD + dd;
                    size_t a1 = (((size_t)((r1 >> 9) * 16 + hh)) * T + (r1 & 511)) * HD + dd;
                    *(__half2*)(pq + a0) = q0;
                    *(__half2*)(pq + a1) = q1;
                } else {
                    __half* dst = (seg == 0) ? pk : pv;
                    __half2 h0 = __floats2half2_rn(v0.x, v0.y);
                    __half2 h1 = __floats2half2_rn(v1.x, v1.y);
                    size_t a0 = (((size_t)((r0 >> 9) * 16 + hh)) * ST + S + (r0 & 511)) * HD + dd;
                    size_t a1 = (((size_t)((r1 >> 9) * 16 + hh)) * ST + S + (r1 & 511)) * HD + dd;
                    *(__half2*)(dst + a0) = h0;
                    *(__half2*)(dst + a1) = h1;
                }
            }
        }
    }
}

// ---------------------------------------------------------------------------
// Flash attention, SPLIT-KV x2 (R17). grid (4, NH, B*2); z = b*2 + half.
// Each CTA handles 10 of 20 KV chunks, writes UNNORMALIZED fp32 partial O
// and partial l to g_po/g_pl. No-max softmax makes merge = plain add.
// ---------------------------------------------------------------------------
#define PROW 144
#define CH 128
#define NCHU_H ((ST / CH) / 2)          // 10 chunks per half
#define KTILE (CH * PROW)
#define ATTN_SMEM (4 * KTILE)

__global__ __launch_bounds__(128, 3)
void attn_h(const __half* __restrict__ kh, const __half* __restrict__ vh,
            const __half* __restrict__ qh)
{
    extern __shared__ char smc[];
    const int tid  = threadIdx.x;
    const int wid  = tid >> 5;
    const int lane = tid & 31;
    const int t0 = blockIdx.x * 128;
    const int h  = blockIdx.y;
    const int half = blockIdx.z & 1;
    const int b  = blockIdx.z >> 1;
    const int sbase = half * (ST / 2);          // 0 or 1280

    const uint32_t Sb  = smem_u32(smc);
    const uint32_t Kb0 = Sb;
    const uint32_t Qb  = Sb + KTILE;
    const uint32_t Vb0 = Sb + 2 * KTILE;

    const __half* khp = kh + ((size_t)(b * NH + h)) * ST * HD + (size_t)sbase * HD;
    const __half* vhp = vh + ((size_t)(b * NH + h)) * ST * HD + (size_t)sbase * HD;
    const __half* qhp = qh + ((size_t)(b * NH + h)) * T * HD + (size_t)t0 * HD;

    // ---- init V pad columns: col 64 = 1.0, cols 65-71 = 0 (both buffers) ----
    {
        uint4 ones = make_uint4(0x00003C00u, 0u, 0u, 0u);
#pragma unroll
        for (int rr = 0; rr < 2; rr++) {
            int r = tid + rr * 128;
            uint32_t addr = Vb0 + (uint32_t)((r >> 7) * KTILE + (r & 127) * PROW + 128);
            asm volatile("st.shared.v4.b32 [%0], {%1,%2,%3,%4};"
                         :: "r"(addr), "r"(ones.x), "r"(ones.y), "r"(ones.z), "r"(ones.w));
        }
    }

    // ---- chunk-0 K/V loads first (overlap with Q staging) ----
#pragma unroll
    for (int u = 0; u < 8; u++) {
        int idx = tid + u * 128;
        int r = idx >> 3, c8 = idx & 7;
        uint32_t doff = (uint32_t)(r * PROW + c8 * 16);
        cp_async16_cg(Kb0 + doff, khp + (size_t)r * HD + c8 * 8);
        cp_async16_cg(Vb0 + doff, vhp + (size_t)r * HD + c8 * 8);
    }
    CP_COMMIT();

    // ---- stage Q into K buffer 1 ----
#pragma unroll
    for (int u = 0; u < 8; u++) {
        int idx = tid + u * 128;
        int r = idx >> 3, c8 = idx & 7;
        cp_async16_cg(Qb + (uint32_t)(r * PROW + c8 * 16), qhp + (size_t)r * HD + c8 * 8);
    }
    CP_COMMIT();
    CP_WAIT(0);
    __syncthreads();

    uint32_t qf[2][4][4];
#pragma unroll
    for (int tm = 0; tm < 2; tm++) {
        uint32_t aoff = (uint32_t)((wid * 32 + tm * 16 + (lane & 15)) * PROW + (lane >> 4) * 16);
#pragma unroll
        for (int ks = 0; ks < 4; ks++)
            ldsm_x4(qf[tm][ks][0], qf[tm][ks][1], qf[tm][ks][2], qf[tm][ks][3],
                    Qb + aoff + ks * 32);
    }
    // Q reads ordered before chunk-1 staging by the loop's first __syncthreads.

    uint32_t koff4[4];
#pragma unroll
    for (int p = 0; p < 4; p++)
        koff4[p] = (uint32_t)((p * 16 + (lane & 7) + ((lane >> 4) & 1) * 8) * PROW
                              + ((lane >> 3) & 1) * 16);
    const uint32_t voff4 = (uint32_t)(((lane & 7) + ((lane >> 3) & 1) * 8) * PROW
                                      + ((lane >> 4) & 1) * 16);

    float O[2][8][4];
#pragma unroll
    for (int tm = 0; tm < 2; tm++)
#pragma unroll
        for (int tn = 0; tn < 8; tn++)
#pragma unroll
            for (int v = 0; v < 4; v++) O[tm][tn][v] = 0.f;
    float Ol[2][4];
#pragma unroll
    for (int tm = 0; tm < 2; tm++)
#pragma unroll
        for (int v = 0; v < 4; v++) Ol[tm][v] = 0.f;

    for (int i = 0; i < NCHU_H; i++) {
        if (i < NCHU_H - 1) {
            __syncthreads();
            const int buf = (i + 1) & 1;
            const uint32_t kb = Kb0 + buf * KTILE;
            const uint32_t vb = Vb0 + buf * KTILE;
            const size_t s0n = (size_t)(i + 1) * CH;
#pragma unroll
            for (int u = 0; u < 8; u++) {
                int idx = tid + u * 128;
                int r = idx >> 3, c8 = idx & 7;
                uint32_t doff = (uint32_t)(r * PROW + c8 * 16);
                cp_async16_cg(kb + doff, khp + (s0n + r) * HD + c8 * 8);
                cp_async16_cg(vb + doff, vhp + (s0n + r) * HD + c8 * 8);
            }
            CP_COMMIT();
            CP_WAIT(1);
        } else {
            CP_WAIT(0);
        }
        __syncthreads();

        const uint32_t kbb = Kb0 + (i & 1) * KTILE;
        const uint32_t vbb = Vb0 + (i & 1) * KTILE;

#pragma unroll
        for (int sub = 0; sub < 2; sub++) {
            const uint32_t kb = kbb + sub * (64 * PROW);
            const uint32_t vb = vbb + sub * (64 * PROW);

            float sf[2][8][4];
#pragma unroll
            for (int tm = 0; tm < 2; tm++)
#pragma unroll
                for (int tn = 0; tn < 8; tn++)
#pragma unroll
                    for (int v = 0; v < 4; v++) sf[tm][tn][v] = 0.f;
#pragma unroll
            for (int ks = 0; ks < 4; ks++) {
                uint32_t bf[8][2];
#pragma unroll
                for (int p = 0; p < 4; p++)
                    ldsm_x4(bf[2 * p][0], bf[2 * p][1], bf[2 * p + 1][0], bf[2 * p + 1][1],
                            kb + koff4[p] + ks * 32);
#pragma unroll
                for (int tm = 0; tm < 2; tm++)
#pragma unroll
                    for (int tn = 0; tn < 8; tn++)
                        mma_f16(sf[tm][tn], qf[tm][ks], bf[tn][0], bf[tn][1]);
            }

            uint32_t ph[2][8][2];
#pragma unroll
            for (int tm = 0; tm < 2; tm++) {
#pragma unroll
                for (int tn = 0; tn < 8; tn++) {
                    __half2 hlo = __floats2half2_rn(sf[tm][tn][0], sf[tm][tn][1]);
                    __half2 hhi = __floats2half2_rn(sf[tm][tn][2], sf[tm][tn][3]);
                    ph[tm][tn][0] = ex2_h2(*(uint32_t*)&hlo);
                    ph[tm][tn][1] = ex2_h2(*(uint32_t*)&hhi);
                }
            }

#pragma unroll
            for (int ks = 0; ks < 4; ks++) {
                uint32_t bv[8][2];
#pragma unroll
                for (int p = 0; p < 4; p++)
                    ldsm_x4_trans(bv[2 * p][0], bv[2 * p][1], bv[2 * p + 1][0], bv[2 * p + 1][1],
                                  vb + voff4 + ks * (16 * PROW) + p * 32);
                uint32_t bl0, bl1;
                ldsm_x2_trans(bl0, bl1, vb + voff4 + ks * (16 * PROW) + 128);
#pragma unroll
                for (int tm = 0; tm < 2; tm++) {
                    uint32_t a[4] = { ph[tm][2 * ks][0],     ph[tm][2 * ks][1],
                                      ph[tm][2 * ks + 1][0], ph[tm][2 * ks + 1][1] };
#pragma unroll
                    for (int tn = 0; tn < 8; tn++)
                        mma_f16(O[tm][tn], a, bv[tn][0], bv[tn][1]);
                    mma_f16(Ol[tm], a, bl0, bl1);
                }
            }
        }
    }

    // ---- epilogue: write UNNORMALIZED fp32 partials + l to scratch ----
    const int rowq = lane >> 2;
    float* pob = g_po + (size_t)half * BHTD
               + ((size_t)(b * NH + h) * T) * HD;
    float* plb = g_pl + (size_t)half * BHT + (size_t)(b * NH + h) * T;
#pragma unroll
    for (int tm = 0; tm < 2; tm++) {
        const int ra = t0 + wid * 32 + tm * 16 + rowq;
        const int ca = (lane & 3) * 2;
        float* o0 = pob + (size_t)ra * HD + ca;
        float* o1 = o0 + (size_t)8 * HD;
#pragma unroll
        for (int tn = 0; tn < 8; tn++) {
            *(float2*)(o0 + tn * 8) = make_float2(O[tm][tn][0], O[tm][tn][1]);
            *(float2*)(o1 + tn * 8) = make_float2(O[tm][tn][2], O[tm][tn][3]);
        }
        if ((lane & 3) == 0) {
            plb[ra]     = Ol[tm][0];
            plb[ra + 8] = Ol[tm][2];
        }
    }
}

// ---------------------------------------------------------------------------
// split-KV reduce: g_wvh = (O0 + O1) / (l0 + l1), fp32 -> half
// ---------------------------------------------------------------------------
__global__ __launch_bounds__(256)
void reduce_kv()
{
    int idx = blockIdx.x * 256 + threadIdx.x;    // 0 .. BHTD/4 - 1
    int d4 = idx & 15;
    int t  = (idx >> 4) & (T - 1);
    int bh = idx >> 13;                          // / (T*16)
    size_t o = ((size_t)bh * T + t) * HD + d4 * 4;

    float4 p0 = *(const float4*)(g_po + o);
    float4 p1 = *(const float4*)(g_po + BHTD + o);
    int lidx = bh * T + t;
    float inv = 1.f / (g_pl[lidx] + g_pl[BHT + lidx]);

    __half2 h0 = __floats2half2_rn((p0.x + p1.x) * inv, (p0.y + p1.y) * inv);
    __half2 h1 = __floats2half2_rn((p0.z + p1.z) * inv, (p0.w + p1.w) * inv);

    int b = bh >> 4, h = bh & 15;
    size_t oo = ((size_t)(b * T + t)) * NS + h * HD + d4 * 4;
    *(uint2*)(g_wvh + oo) = make_uint2(*(uint32_t*)&h0, *(uint32_t*)&h1);
}

// ---------------------------------------------------------------------------
// kernel_launch
// ---------------------------------------------------------------------------
extern "C" void kernel_launch(void* const* d_in, const int* in_sizes, int n_in,
                              void* d_out, int out_size)
{
    const float* x  = (const float*)d_in[0];
    const float* kv = (const float*)d_in[1];
    const float* Wq = (const float*)d_in[3];
    const float* bq = (const float*)d_in[4];
    const float* Wk = (const float*)d_in[5];
    const float* Wv = (const float*)d_in[6];
    const float* bv = (const float*)d_in[7];
    const float* Wo = (const float*)d_in[8];
    const float* bo = (const float*)d_in[9];

    float* out  = (float*)d_out;
    float* keyo = out + (size_t)BT * NS;
    float* valo = keyo + (size_t)BT * NS;

    __half *xh, *wvh, *wth, *khb, *vhb, *qhb;
    cudaGetSymbolAddress((void**)&xh, g_xh);
    cudaGetSymbolAddress((void**)&wvh, g_wvh);
    cudaGetSymbolAddress((void**)&wth, g_wth);
    cudaGetSymbolAddress((void**)&khb, g_kh);
    cudaGetSymbolAddress((void**)&vhb, g_vh);
    cudaGetSymbolAddress((void**)&qhb, g_qh);
    __half* wtO = wth + (size_t)3 * NS * NS;

    cudaFuncSetAttribute(gemm_h3, cudaFuncAttributeMaxDynamicSharedMemorySize, GEMM_SMEM);
    cudaFuncSetAttribute(attn_h, cudaFuncAttributeMaxDynamicSharedMemorySize, ATTN_SMEM);

    // prep: weight transposes + x conversion in one launch
    dim3 tb(32, 8), tg(32, 32, 5);
    prep_h<<<tg, tb>>>(Wk, Wv, Wq, Wo, wth, x, xh);

    // fused QKV projection + KV-cache pack filler CTAs
    dim3 gq(GEMM_XBLKS + PACK_XBLKS, 32);
    gemm_h3<<<gq, 256, GEMM_SMEM>>>(xh, wth, nullptr, bv, bq,
                                    keyo, valo, nullptr, khb, vhb, qhb, kv);

    // split-KV attention (z = b*2 + half) + reduce
    dim3 ag(T / 128, NH, B * 2);
    attn_h<<<ag, 128, ATTN_SMEM>>>(khb, vhb, qhb);
    reduce_kv<<<(int)(BHTD / 4 / 256), 256>>>();

    dim3 go(8, 32);
    gemm_h3<<<go, 256, GEMM_SMEM>>>(wvh, wtO, bo, bo, bo,
                                    out, out, out, nullptr, nullptr, nullptr, nullptr);
}